// round 11
// baseline (speedup 1.0000x reference)
#include <cuda_runtime.h>
#include <cuda_bf16.h>
#include <cstdint>

typedef unsigned long long ull;
#define B_TOT 1024
#define T_LEN 512
#define NU 64
#define NB 8
#define THR 256

__device__ float g_h[(size_t)B_TOT * T_LEN * NU];

__device__ __forceinline__ float sigf(float x) {
    float t; asm("tanh.approx.f32 %0, %1;" : "=f"(t) : "f"(0.5f * x));
    return fmaf(0.5f, t, 0.5f);
}
__device__ __forceinline__ uint32_t pack_bf2(__nv_bfloat16 a, __nv_bfloat16 b) {
    __nv_bfloat162 p; p.x = a; p.y = b; return *(uint32_t*)&p;
}
__device__ __forceinline__ void hmma(float* c, const uint32_t* a, uint32_t b0, uint32_t b1) {
    asm volatile("mma.sync.aligned.m16n8k16.row.col.f32.bf16.bf16.f32 "
        "{%0,%1,%2,%3}, {%4,%5,%6,%7}, {%8,%9}, {%0,%1,%2,%3};"
        : "+f"(c[0]), "+f"(c[1]), "+f"(c[2]), "+f"(c[3])
        : "r"(a[0]), "r"(a[1]), "r"(a[2]), "r"(a[3]), "r"(b0), "r"(b1));
}
__device__ __forceinline__ uint32_t smem_u32(const void* p) {
    uint32_t a;
    asm("{ .reg .u64 t; cvta.to.shared.u64 t, %1; cvt.u32.u64 %0, t; }" : "=r"(a) : "l"(p));
    return a;
}
__device__ __forceinline__ uint32_t mapa_u32(uint32_t a, uint32_t r) {
    uint32_t q; asm("mapa.shared::cluster.u32 %0, %1, %2;" : "=r"(q) : "r"(a), "r"(r));
    return q;
}
__device__ __forceinline__ uint32_t ctarank() {
    uint32_t r; asm("mov.u32 %0, %%cluster_ctarank;" : "=r"(r)); return r;
}
__device__ __forceinline__ void sts_u16_remote(uint32_t addr, __nv_bfloat16 v) {
    unsigned short s = *(unsigned short*)&v;
    asm volatile("st.shared::cluster.u16 [%0], %1;" :: "r"(addr), "h"(s) : "memory");
}
__device__ __forceinline__ void arrive_local(uint32_t a) {
    asm volatile("mbarrier.arrive.release.cta.shared::cta.b64 _, [%0];" :: "r"(a) : "memory");
}
__device__ __forceinline__ void arrive_remote(uint32_t a) {
    asm volatile("mbarrier.arrive.release.cluster.shared::cluster.b64 _, [%0];" :: "r"(a) : "memory");
}
__device__ __forceinline__ void mwait(uint32_t m, uint32_t ph) {
    asm volatile("{\n\t.reg .pred P1;\n\tWL_%=:\n\t"
        "mbarrier.try_wait.parity.acquire.cluster.shared::cta.b64 P1, [%0], %1, 0x989680;\n\t"
        "@P1 bra.uni WD_%=;\n\tbra.uni WL_%=;\n\tWD_%=:\n\t}" :: "r"(m), "r"(ph) : "memory");
}
#define CLUSTER_SYNC() do { \
    asm volatile("barrier.cluster.arrive.aligned;" ::: "memory"); \
    asm volatile("barrier.cluster.wait.aligned;" ::: "memory"); } while (0)

// 2-CTA cluster = 8 batch rows; rank r owns gate-cols of units [32r,32r+32).
// act[buf][8][P]: k<KX x-part (prev-layer h, all 64 units), k>=KX h-part.
// Per step: MMA (W frags in regs, 3 hi/lo terms), lane transpose, epilogue,
// h hi/lo stored local+remote (DSMEM), mbarrier(512) release/acquire.
template <int KX, bool LAST>
__global__ void __launch_bounds__(THR, 2) __cluster_dims__(2, 1, 1)
lstm_layer(const float* __restrict__ xin, const float* __restrict__ Wx,
           const float* __restrict__ U,   const float* __restrict__ bias)
{
    constexpr int KTOT = KX + NU;
    constexpr int KS   = KTOT / 16;
    constexpr int P    = 2 * KTOT + 8;

    __shared__ __nv_bfloat16 act[2][NB * P];
    __shared__ float Xsh[2][NB];
    __shared__ ull mbar;

    const int tid = threadIdx.x, wid = tid >> 5, lane = tid & 31;
    const int lr = lane >> 2, qq = lane & 3;
    const int aa = lr >> 2, gg = lr & 3;
    const uint32_t rank = ctarank();
    const int bg0 = (blockIdx.x >> 1) * NB;
    const int u = 32 * (int)rank + 4 * wid + (aa + 2 * (gg >> 1)); // owned unit
    const int b = 2 * qq + (gg & 1);                               // owned batch
    const int u_alt = u ^ 32;

    const uint32_t mb = smem_u32(&mbar);
    const uint32_t mb_peer = mapa_u32(mb, rank ^ 1);
    const uint32_t act_peer0 = mapa_u32(smem_u32(&act[0][0]), rank ^ 1);

    // W fragments: local col m in [16*wid,16*wid+16); unit=32r+(m>>2), gate=m&3
    uint32_t Whi[KS][4], Wlo[KS][4];
    {
        const int m0 = 16 * wid + lr;
        #pragma unroll
        for (int s = 0; s < KS; ++s) {
            const int kb = 16 * s + 2 * qq;
            #pragma unroll
            for (int i = 0; i < 4; ++i) {
                const int k = kb + ((i >> 1) << 3);
                const int m = m0 + ((i & 1) << 3);
                const int oc = 32 * (int)rank + (m >> 2) + 64 * (m & 3);
                float f0 = (k < KX) ? Wx[(size_t)k * 256 + oc]
                                    : U[(size_t)(k - KX) * 256 + oc];
                float f1 = (k + 1 < KX) ? Wx[(size_t)(k + 1) * 256 + oc]
                                        : U[(size_t)(k + 1 - KX) * 256 + oc];
                __nv_bfloat16 h0 = __float2bfloat16(f0), h1 = __float2bfloat16(f1);
                Whi[s][i] = pack_bf2(h0, h1);
                Wlo[s][i] = pack_bf2(__float2bfloat16(f0 - __bfloat162float(h0)),
                                     __float2bfloat16(f1 - __bfloat162float(h1)));
            }
        }
    }
    float bg[4], wxg[4];
    #pragma unroll
    for (int g = 0; g < 4; ++g) {
        bg[g]  = bias[u + 64 * g];
        wxg[g] = (KX == 0) ? Wx[u + 64 * g] : 0.0f;
    }

    for (int i = tid; i < 2 * NB * P; i += THR) act[0][i] = __float2bfloat16(0.0f);
    if (tid == 0) { asm volatile("mbarrier.init.shared.b64 [%0], %1;" :: "r"(mb), "r"(512) : "memory"); }

    float cs = 0.0f;
    if (KX == 0) {
        if (tid < NB) Xsh[0][tid] = xin[(size_t)(bg0 + tid) * T_LEN + 0];
    } else {   // stage x-part t=0: 2 units per thread
        float v0 = g_h[((size_t)(bg0 + b) * T_LEN) * NU + u];
        float v1 = g_h[((size_t)(bg0 + b) * T_LEN) * NU + u_alt];
        __nv_bfloat16 h0 = __float2bfloat16(v0), h1 = __float2bfloat16(v1);
        act[0][b * P + u] = h0;
        act[0][b * P + KTOT + u] = __float2bfloat16(v0 - __bfloat162float(h0));
        act[0][b * P + u_alt] = h1;
        act[0][b * P + KTOT + u_alt] = __float2bfloat16(v1 - __bfloat162float(h1));
    }
    __syncthreads();
    CLUSTER_SYNC();

    for (int t = 0; t < T_LEN; ++t) {
        const int p = t & 1;
        const int tn = (t + 1 < T_LEN) ? t + 1 : T_LEN - 1;
        float vn0 = 0.0f, vn1 = 0.0f, xvn = 0.0f;
        if (KX == 0) {
            if (tid < NB) xvn = xin[(size_t)(bg0 + tid) * T_LEN + tn];
        } else {
            vn0 = g_h[((size_t)(bg0 + b) * T_LEN + tn) * NU + u];
            vn1 = g_h[((size_t)(bg0 + b) * T_LEN + tn) * NU + u_alt];
        }

        // MMA: 3 hi/lo terms x KS, 4 acc chains
        float a4[16] = {0,0,0,0, 0,0,0,0, 0,0,0,0, 0,0,0,0};
        const __nv_bfloat16* ap = act[p];
        #pragma unroll
        for (int s = 0; s < KS; ++s) {
            const uint32_t* bp = (const uint32_t*)(ap + lr * P + 16 * s + 2 * qq);
            uint32_t bh0 = bp[0], bh1 = bp[4];
            uint32_t bl0 = bp[KTOT / 2], bl1 = bp[KTOT / 2 + 4];
            float* acc = a4 + 4 * (s & 3);
            hmma(acc, Whi[s], bh0, bh1);
            hmma(acc, Whi[s], bl0, bl1);
            hmma(acc, Wlo[s], bh0, bh1);
        }
        float z0 = (a4[0]+a4[4])+(a4[8]+a4[12]);
        float z1 = (a4[1]+a4[5])+(a4[9]+a4[13]);
        float z2 = (a4[2]+a4[6])+(a4[10]+a4[14]);
        float z3 = (a4[3]+a4[7])+(a4[11]+a4[15]);

        { // 4x4 lane transpose over lane bits 2-3
            const bool g0 = (lane & 4), g1 = (lane & 8);
            float sA = g0 ? z0 : z1, sB = g0 ? z2 : z3;
            float tA = __shfl_xor_sync(~0u, sA, 4), tB = __shfl_xor_sync(~0u, sB, 4);
            if (!g0) { z1 = tA; z3 = tB; } else { z0 = tA; z2 = tB; }
            float sC = g1 ? z0 : z2, sD = g1 ? z1 : z3;
            float tC = __shfl_xor_sync(~0u, sC, 8), tD = __shfl_xor_sync(~0u, sD, 8);
            if (!g1) { z2 = tC; z3 = tD; } else { z0 = tC; z1 = tD; }
        }

        float zi = z0 + bg[0], zf = z1 + bg[1], zg = z2 + bg[2], zo = z3 + bg[3];
        if (KX == 0) {
            float xr = Xsh[p][b];
            zi = fmaf(xr, wxg[0], zi); zf = fmaf(xr, wxg[1], zf);
            zg = fmaf(xr, wxg[2], zg); zo = fmaf(xr, wxg[3], zo);
        }
        float cn = fmaf(sigf(zf), cs, sigf(zi) * fmaxf(zg, 0.0f));
        cs = cn;
        float h = sigf(zo) * fmaxf(cn, 0.0f);

        // write buf p^1: own h (hi/lo) local + remote; x-part local
        __nv_bfloat16* an = act[p ^ 1];
        const uint32_t an_peer = act_peer0 + (uint32_t)((p ^ 1) * NB * P) * 2;
        __nv_bfloat16 hh = __float2bfloat16(h);
        __nv_bfloat16 hl = __float2bfloat16(h - __bfloat162float(hh));
        an[b * P + KX + u] = hh;
        an[b * P + KTOT + KX + u] = hl;
        sts_u16_remote(an_peer + (uint32_t)(b * P + KX + u) * 2, hh);
        sts_u16_remote(an_peer + (uint32_t)(b * P + KTOT + KX + u) * 2, hl);
        if (KX == 0) {
            if (tid < NB) Xsh[p ^ 1][tid] = xvn;
        } else {
            __nv_bfloat16 x0 = __float2bfloat16(vn0), x1 = __float2bfloat16(vn1);
            an[b * P + u] = x0;
            an[b * P + KTOT + u] = __float2bfloat16(vn0 - __bfloat162float(x0));
            an[b * P + u_alt] = x1;
            an[b * P + KTOT + u_alt] = __float2bfloat16(vn1 - __bfloat162float(x1));
        }
        if (!LAST || t == T_LEN - 1)
            g_h[((size_t)(bg0 + b) * T_LEN + t) * NU + u] = h;

        arrive_local(mb);
        arrive_remote(mb_peer);
        mwait(mb, t & 1);
    }
    CLUSTER_SYNC();
}

__global__ void __launch_bounds__(256)
head_kernel(const float* __restrict__ Wd, const float* __restrict__ bd,
            float* __restrict__ out)
{
    __shared__ float wd[NU];
    if (threadIdx.x < NU) wd[threadIdx.x] = Wd[threadIdx.x];
    __syncthreads();
    int b = blockIdx.x * blockDim.x + threadIdx.x;
    const float* hp = g_h + ((size_t)b * T_LEN + (T_LEN - 1)) * NU;
    float s = 0.0f;
    #pragma unroll
    for (int u = 0; u < NU; ++u) s += hp[u] * wd[u];
    out[b] = s + bd[0];
}

extern "C" void kernel_launch(void* const* d_in, const int* in_sizes, int n_in,
                              void* d_out, int out_size)
{
    const float* x   = (const float*)d_in[0];
    const float* Wx0 = (const float*)d_in[1];
    const float* U0  = (const float*)d_in[2];
    const float* b0  = (const float*)d_in[3];
    const float* Wx1 = (const float*)d_in[4];
    const float* U1  = (const float*)d_in[5];
    const float* b1  = (const float*)d_in[6];
    const float* Wx2 = (const float*)d_in[7];
    const float* U2  = (const float*)d_in[8];
    const float* b2  = (const float*)d_in[9];
    const float* Wx3 = (const float*)d_in[10];
    const float* U3  = (const float*)d_in[11];
    const float* b3  = (const float*)d_in[12];
    const float* Wd  = (const float*)d_in[13];
    const float* bd  = (const float*)d_in[14];
    float* out = (float*)d_out;

    lstm_layer<0,  false><<<256, THR>>>(x,       Wx0, U0, b0);
    lstm_layer<64, false><<<256, THR>>>(nullptr, Wx1, U1, b1);
    lstm_layer<64, false><<<256, THR>>>(nullptr, Wx2, U2, b2);
    lstm_layer<64, true ><<<256, THR>>>(nullptr, Wx3, U3, b3);
    head_kernel<<<B_TOT / 256, 256>>>(Wd, bd, out);
}

// round 12
// speedup vs baseline: 1.3118x; 1.3118x over previous
#include <cuda_runtime.h>
#include <cuda_bf16.h>
#include <cstdint>

typedef unsigned long long ull;
#define B_TOT 1024
#define T_LEN 512
#define NU 64
#define NB 8
#define NG 2          // batch groups per CTA
#define THR 512

__device__ float g_h[(size_t)B_TOT * T_LEN * NU];

__device__ __forceinline__ float sigf(float x) {
    float t; asm("tanh.approx.f32 %0, %1;" : "=f"(t) : "f"(0.5f * x));
    return fmaf(0.5f, t, 0.5f);
}
__device__ __forceinline__ uint32_t pack_bf2(__nv_bfloat16 a, __nv_bfloat16 b) {
    __nv_bfloat162 p; p.x = a; p.y = b; return *(uint32_t*)&p;
}
__device__ __forceinline__ void hmma(float* c, const uint32_t* a, uint32_t b0, uint32_t b1) {
    asm volatile("mma.sync.aligned.m16n8k16.row.col.f32.bf16.bf16.f32 "
        "{%0,%1,%2,%3}, {%4,%5,%6,%7}, {%8,%9}, {%0,%1,%2,%3};"
        : "+f"(c[0]), "+f"(c[1]), "+f"(c[2]), "+f"(c[3])
        : "r"(a[0]), "r"(a[1]), "r"(a[2]), "r"(a[3]), "r"(b0), "r"(b1));
}

// Two independent 8-row batch groups per CTA (grid = 64). W fragments shared
// in registers; per step: MMA_A, MMA_B issued back-to-back (independent
// chains), then epilogue_A / epilogue_B; ONE __syncthreads per step covers
// both groups. Gate-interleaved columns + 4x4 lane transpose as in R8.
// z = Whi*Ahi + Whi*Alo + Wlo*Ahi (bf16 hi/lo compensation).
template <int KX, bool LAST>
__global__ void __launch_bounds__(THR, 1)
lstm_layer(const float* __restrict__ xin, const float* __restrict__ Wx,
           const float* __restrict__ U,   const float* __restrict__ bias)
{
    constexpr int KTOT = KX + NU;       // 128 or 64
    constexpr int KS   = KTOT / 16;     // 8 or 4
    constexpr int P    = 2 * KTOT + 8;  // bf16 pitch

    __shared__ __nv_bfloat16 act[2][NG][NB * P];  // [buf][group][row*P+k]
    __shared__ float Xsh[2][NG][NB];

    const int tid  = threadIdx.x;
    const int wid  = tid >> 5;
    const int lane = tid & 31;
    const int lr   = lane >> 2;
    const int qq   = lane & 3;
    const int aa   = lr >> 2;
    const int gg   = lr & 3;
    const int bg0  = blockIdx.x * (NG * NB);

    const int u = 4 * wid + (aa + 2 * (gg >> 1));  // owned unit (per group)
    const int b = 2 * qq + (gg & 1);               // owned batch row (per group)

    // ---- W fragments (gate-interleaved columns), shared by both groups ----
    uint32_t Whi[KS][4], Wlo[KS][4];
    {
        const int m0 = 16 * wid + lr;
        #pragma unroll
        for (int s = 0; s < KS; ++s) {
            const int kb = 16 * s + 2 * qq;
            #pragma unroll
            for (int i = 0; i < 4; ++i) {
                const int k = kb + ((i >> 1) << 3);
                const int m = m0 + ((i & 1) << 3);
                const int oc = (m >> 2) + 64 * (m & 3);
                float f0 = (k < KX) ? Wx[(size_t)k * 256 + oc]
                                    : U[(size_t)(k - KX) * 256 + oc];
                float f1 = (k + 1 < KX) ? Wx[(size_t)(k + 1) * 256 + oc]
                                        : U[(size_t)(k + 1 - KX) * 256 + oc];
                __nv_bfloat16 h0 = __float2bfloat16(f0), h1 = __float2bfloat16(f1);
                Whi[s][i] = pack_bf2(h0, h1);
                Wlo[s][i] = pack_bf2(__float2bfloat16(f0 - __bfloat162float(h0)),
                                     __float2bfloat16(f1 - __bfloat162float(h1)));
            }
        }
    }
    float bg[4], wxg[4];
    #pragma unroll
    for (int g = 0; g < 4; ++g) {
        bg[g]  = bias[u + 64 * g];
        wxg[g] = (KX == 0) ? Wx[u + 64 * g] : 0.0f;
    }

    for (int i = tid; i < 2 * NG * NB * P; i += THR)
        (&act[0][0][0])[i] = __float2bfloat16(0.0f);

    // ---- stage t=0 inputs for both groups ----
    float csA = 0.0f, csB = 0.0f;
    if (KX == 0) {
        if (tid < NG * NB)
            Xsh[0][tid >> 3][tid & 7] =
                xin[(size_t)(bg0 + tid) * T_LEN + 0];
    } else {
        #pragma unroll
        for (int g = 0; g < NG; ++g) {
            float v = g_h[((size_t)(bg0 + g * NB + b) * T_LEN) * NU + u];
            __nv_bfloat16 vh = __float2bfloat16(v);
            act[0][g][b * P + u]        = vh;
            act[0][g][b * P + KTOT + u] = __float2bfloat16(v - __bfloat162float(vh));
        }
    }

    for (int t = 0; t < T_LEN; ++t) {
        const int p = t & 1;
        __syncthreads();   // buf[p] complete for both groups

        // prefetch t+1 inputs
        const int tn = (t + 1 < T_LEN) ? t + 1 : T_LEN - 1;
        float vnA = 0.0f, vnB = 0.0f, xvn = 0.0f;
        if (KX == 0) {
            if (tid < NG * NB) xvn = xin[(size_t)(bg0 + tid) * T_LEN + tn];
        } else {
            vnA = g_h[((size_t)(bg0 + b) * T_LEN + tn) * NU + u];
            vnB = g_h[((size_t)(bg0 + NB + b) * T_LEN + tn) * NU + u];
        }

        // ---- MMA for both groups (independent chains, 2 per group) ----
        float accA[8] = {0,0,0,0, 0,0,0,0};
        float accB[8] = {0,0,0,0, 0,0,0,0};
        const __nv_bfloat16* apA = act[p][0];
        const __nv_bfloat16* apB = act[p][1];
        #pragma unroll
        for (int s = 0; s < KS; ++s) {
            const int off = lr * P + 16 * s + 2 * qq;
            const uint32_t* bpA = (const uint32_t*)(apA + off);
            float* aA = accA + 4 * (s & 1);
            hmma(aA, Whi[s], bpA[0], bpA[4]);
            hmma(aA, Whi[s], bpA[KTOT / 2], bpA[KTOT / 2 + 4]);
            hmma(aA, Wlo[s], bpA[0], bpA[4]);
            const uint32_t* bpB = (const uint32_t*)(apB + off);
            float* aB = accB + 4 * (s & 1);
            hmma(aB, Whi[s], bpB[0], bpB[4]);
            hmma(aB, Whi[s], bpB[KTOT / 2], bpB[KTOT / 2 + 4]);
            hmma(aB, Wlo[s], bpB[0], bpB[4]);
        }

        __nv_bfloat16* anA = act[p ^ 1][0];
        __nv_bfloat16* anB = act[p ^ 1][1];

        #pragma unroll
        for (int g = 0; g < NG; ++g) {
            float* acc = g ? accB : accA;
            float z0 = acc[0] + acc[4], z1 = acc[1] + acc[5];
            float z2 = acc[2] + acc[6], z3 = acc[3] + acc[7];
            { // 4x4 lane transpose over lane bits 2-3
                const bool b0g = (lane & 4), b1g = (lane & 8);
                float sA = b0g ? z0 : z1, sB = b0g ? z2 : z3;
                float tA = __shfl_xor_sync(~0u, sA, 4), tB = __shfl_xor_sync(~0u, sB, 4);
                if (!b0g) { z1 = tA; z3 = tB; } else { z0 = tA; z2 = tB; }
                float sC = b1g ? z0 : z2, sD = b1g ? z1 : z3;
                float tC = __shfl_xor_sync(~0u, sC, 8), tD = __shfl_xor_sync(~0u, sD, 8);
                if (!b1g) { z2 = tC; z3 = tD; } else { z0 = tC; z1 = tD; }
            }
            float zi = z0 + bg[0], zf = z1 + bg[1], zg = z2 + bg[2], zo = z3 + bg[3];
            if (KX == 0) {
                float xr = Xsh[p][g][b];
                zi = fmaf(xr, wxg[0], zi); zf = fmaf(xr, wxg[1], zf);
                zg = fmaf(xr, wxg[2], zg); zo = fmaf(xr, wxg[3], zo);
            }
            float cprev = g ? csB : csA;
            float cn = fmaf(sigf(zf), cprev, sigf(zi) * fmaxf(zg, 0.0f));
            if (g) csB = cn; else csA = cn;
            float h = sigf(zo) * fmaxf(cn, 0.0f);

            __nv_bfloat16* an = g ? anB : anA;
            __nv_bfloat16 hh = __float2bfloat16(h);
            an[b * P + KX + u]        = hh;
            an[b * P + KTOT + KX + u] = __float2bfloat16(h - __bfloat162float(hh));
            if (KX != 0) {
                float vn = g ? vnB : vnA;
                __nv_bfloat16 xh = __float2bfloat16(vn);
                an[b * P + u]        = xh;
                an[b * P + KTOT + u] = __float2bfloat16(vn - __bfloat162float(xh));
            }
            if (!LAST || t == T_LEN - 1)
                g_h[((size_t)(bg0 + g * NB + b) * T_LEN + t) * NU + u] = h;
        }
        if (KX == 0 && tid < NG * NB) Xsh[p ^ 1][tid >> 3][tid & 7] = xvn;
    }
}

__global__ void __launch_bounds__(256)
head_kernel(const float* __restrict__ Wd, const float* __restrict__ bd,
            float* __restrict__ out)
{
    __shared__ float wd[NU];
    if (threadIdx.x < NU) wd[threadIdx.x] = Wd[threadIdx.x];
    __syncthreads();
    int b = blockIdx.x * blockDim.x + threadIdx.x;
    const float* hp = g_h + ((size_t)b * T_LEN + (T_LEN - 1)) * NU;
    float s = 0.0f;
    #pragma unroll
    for (int u = 0; u < NU; ++u) s += hp[u] * wd[u];
    out[b] = s + bd[0];
}

extern "C" void kernel_launch(void* const* d_in, const int* in_sizes, int n_in,
                              void* d_out, int out_size)
{
    const float* x   = (const float*)d_in[0];
    const float* Wx0 = (const float*)d_in[1];
    const float* U0  = (const float*)d_in[2];
    const float* b0  = (const float*)d_in[3];
    const float* Wx1 = (const float*)d_in[4];
    const float* U1  = (const float*)d_in[5];
    const float* b1  = (const float*)d_in[6];
    const float* Wx2 = (const float*)d_in[7];
    const float* U2  = (const float*)d_in[8];
    const float* b2  = (const float*)d_in[9];
    const float* Wx3 = (const float*)d_in[10];
    const float* U3  = (const float*)d_in[11];
    const float* b3  = (const float*)d_in[12];
    const float* Wd  = (const float*)d_in[13];
    const float* bd  = (const float*)d_in[14];
    float* out = (float*)d_out;

    const int NCTA = B_TOT / (NG * NB);   // 64
    lstm_layer<0,  false><<<NCTA, THR>>>(x,       Wx0, U0, b0);
    lstm_layer<64, false><<<NCTA, THR>>>(nullptr, Wx1, U1, b1);
    lstm_layer<64, false><<<NCTA, THR>>>(nullptr, Wx2, U2, b2);
    lstm_layer<64, true ><<<NCTA, THR>>>(nullptr, Wx3, U3, b3);
    head_kernel<<<B_TOT / 256, 256>>>(Wd, bd, out);
}

// round 13
// speedup vs baseline: 1.7307x; 1.3193x over previous
#include <cuda_runtime.h>
#include <cuda_bf16.h>
#include <cstdint>

#define B_TOT 1024
#define T_LEN 512
#define NU 64
#define NB 8
#define THR 512

__device__ float g_h1[(size_t)B_TOT * T_LEN * NU];   // layer1 outputs
__device__ float g_h3[B_TOT * NU];                   // layer3 final h

__device__ __forceinline__ float sigf(float x) {
    float t; asm("tanh.approx.f32 %0, %1;" : "=f"(t) : "f"(0.5f * x));
    return fmaf(0.5f, t, 0.5f);
}
__device__ __forceinline__ uint32_t pack_bf2(__nv_bfloat16 a, __nv_bfloat16 b) {
    __nv_bfloat162 p; p.x = a; p.y = b; return *(uint32_t*)&p;
}
__device__ __forceinline__ void hmma(float* c, const uint32_t* a, uint32_t b0, uint32_t b1) {
    asm volatile("mma.sync.aligned.m16n8k16.row.col.f32.bf16.bf16.f32 "
        "{%0,%1,%2,%3}, {%4,%5,%6,%7}, {%8,%9}, {%0,%1,%2,%3};"
        : "+f"(c[0]), "+f"(c[1]), "+f"(c[2]), "+f"(c[3])
        : "r"(a[0]), "r"(a[1]), "r"(a[2]), "r"(a[3]), "r"(b0), "r"(b1));
}

// Load W fragments for one layer: Whi -> regs, Wlo -> smem frag slots.
__device__ __forceinline__ void load_wfrags(
    const float* Wxp, const float* Up, int KXp, int KS,
    int wid, int lr, int qq, int lane, uint32_t Whi[][4], uint4* wslot)
{
    const int m0 = 16 * wid + lr;
    for (int s = 0; s < KS; ++s) {
        uint32_t wl[4];
        for (int i = 0; i < 4; ++i) {
            const int k = 16 * s + 2 * qq + ((i >> 1) << 3);
            const int m = m0 + ((i & 1) << 3);
            const int oc = (m >> 2) + 64 * (m & 3);
            float f0 = (k < KXp) ? Wxp[(size_t)k * 256 + oc]
                                 : Up[(size_t)(k - KXp) * 256 + oc];
            float f1 = (k + 1 < KXp) ? Wxp[(size_t)(k + 1) * 256 + oc]
                                     : Up[(size_t)(k + 1 - KXp) * 256 + oc];
            __nv_bfloat16 h0 = __float2bfloat16(f0), h1 = __float2bfloat16(f1);
            Whi[s][i] = pack_bf2(h0, h1);
            wl[i] = pack_bf2(__float2bfloat16(f0 - __bfloat162float(h0)),
                             __float2bfloat16(f1 - __bfloat162float(h1)));
        }
        wslot[s * 32 + lane] = make_uint4(wl[0], wl[1], wl[2], wl[3]);
    }
}

// Layer-pair pipeline: stream a = layer L (step tau), stream b = layer L+1
// (step tau-1). FIRST: a=L0 (K=64 + rank-1 scalar x), b=L1 (h1 -> g_h1).
// !FIRST: a=L2 (x = h1 LDG), b=L3 (g_h3 at last step).
// act layout per stream: [buf][row*P + k], hi k<KT, lo at KT+k.
template <int KXA, bool FIRST>
__global__ void __launch_bounds__(THR, 1)
lstm_pair(const float* __restrict__ xin,
          const float* __restrict__ WxA, const float* __restrict__ UA,
          const float* __restrict__ bA,
          const float* __restrict__ WxB, const float* __restrict__ UB,
          const float* __restrict__ bB)
{
    constexpr int KTA = KXA + NU, KSA = KTA / 16, PA = 2 * KTA + 8;
    constexpr int KTB = 128, KSB = 8, PB = 2 * KTB + 8;
    constexpr int WLO_BYTES = 2 * 16 * 8 * 32 * 16;

    extern __shared__ char sm[];
    uint4* wlo = (uint4*)sm;
    __nv_bfloat16* actA = (__nv_bfloat16*)(sm + WLO_BYTES);
    __nv_bfloat16* actB = actA + 2 * NB * PA;
    __shared__ float Xsh[2][NB];

    const int tid = threadIdx.x, wid = tid >> 5, lane = tid & 31;
    const int lr = lane >> 2, qq = lane & 3;
    const int aa = lr >> 2, gg = lr & 3;
    const int bg0 = blockIdx.x * NB;
    const int u = 4 * wid + (aa + 2 * (gg >> 1));
    const int b = 2 * qq + (gg & 1);

    uint32_t WhiA[KSA][4], WhiB[KSB][4];
    uint4* slotA = wlo + (size_t)((0 * 16 + wid) * 8) * 32;
    uint4* slotB = wlo + (size_t)((1 * 16 + wid) * 8) * 32;
    load_wfrags(WxA, UA, KXA, KSA, wid, lr, qq, lane, WhiA, slotA);
    load_wfrags(WxB, UB, 64,  KSB, wid, lr, qq, lane, WhiB, slotB);

    float bgA[4], wxgA[4], bgB[4];
    #pragma unroll
    for (int g = 0; g < 4; ++g) {
        bgA[g] = bA[u + 64 * g];
        wxgA[g] = FIRST ? WxA[u + 64 * g] : 0.0f;
        bgB[g] = bB[u + 64 * g];
    }

    for (int i = tid; i < 2 * NB * PA; i += THR) actA[i] = __float2bfloat16(0.0f);
    for (int i = tid; i < 2 * NB * PB; i += THR) actB[i] = __float2bfloat16(0.0f);

    // stage stream-a step-0 input
    if (FIRST) {
        if (tid < NB) Xsh[0][tid] = xin[(size_t)(bg0 + tid) * T_LEN + 0];
    } else {
        float v = g_h1[((size_t)(bg0 + b) * T_LEN + 0) * NU + u];
        __nv_bfloat16 vh = __float2bfloat16(v);
        actA[b * PA + u] = vh;
        actA[b * PA + KTA + u] = __float2bfloat16(v - __bfloat162float(vh));
    }
    float csA = 0.0f, csB = 0.0f;

    for (int tau = 0; tau <= T_LEN; ++tau) {
        __syncthreads();
        const int pa = tau & 1, pb = pa ^ 1;
        const bool runA = (tau < T_LEN), runB = (tau >= 1);
        float accA[8] = {0,0,0,0,0,0,0,0}, accB[8] = {0,0,0,0,0,0,0,0};

        if (runA) {
            const __nv_bfloat16* ap = actA + pa * NB * PA;
            #pragma unroll
            for (int s = 0; s < KSA; ++s) {
                const uint32_t* bp = (const uint32_t*)(ap + lr * PA + 16 * s + 2 * qq);
                uint4 wl = slotA[s * 32 + lane];
                float* ac = accA + 4 * (s & 1);
                hmma(ac, WhiA[s], bp[0], bp[4]);
                hmma(ac, WhiA[s], bp[KTA / 2], bp[KTA / 2 + 4]);
                hmma(ac, (const uint32_t*)&wl, bp[0], bp[4]);
            }
        }
        if (runB) {
            const __nv_bfloat16* ap = actB + pb * NB * PB;
            #pragma unroll
            for (int s = 0; s < KSB; ++s) {
                const uint32_t* bp = (const uint32_t*)(ap + lr * PB + 16 * s + 2 * qq);
                uint4 wl = slotB[s * 32 + lane];
                float* ac = accB + 4 * (s & 1);
                hmma(ac, WhiB[s], bp[0], bp[4]);
                hmma(ac, WhiB[s], bp[KTB / 2], bp[KTB / 2 + 4]);
                hmma(ac, (const uint32_t*)&wl, bp[0], bp[4]);
            }
        }

        // prefetch stream-a input for tick tau+1
        float vx = 0.0f, xs = 0.0f;
        if (FIRST) {
            if (tid < NB && tau + 1 < T_LEN)
                xs = xin[(size_t)(bg0 + tid) * T_LEN + tau + 1];
        } else if (tau + 1 < T_LEN) {
            vx = g_h1[((size_t)(bg0 + b) * T_LEN + tau + 1) * NU + u];
        }

        if (runA) {   // epilogue a (step tau)
            float z0 = accA[0] + accA[4], z1 = accA[1] + accA[5];
            float z2 = accA[2] + accA[6], z3 = accA[3] + accA[7];
            const bool t0 = (lane & 4), t1 = (lane & 8);
            float sA = t0 ? z0 : z1, sB = t0 ? z2 : z3;
            float tA = __shfl_xor_sync(~0u, sA, 4), tB = __shfl_xor_sync(~0u, sB, 4);
            if (!t0) { z1 = tA; z3 = tB; } else { z0 = tA; z2 = tB; }
            float sC = t1 ? z0 : z2, sD = t1 ? z1 : z3;
            float tC = __shfl_xor_sync(~0u, sC, 8), tD = __shfl_xor_sync(~0u, sD, 8);
            if (!t1) { z2 = tC; z3 = tD; } else { z0 = tC; z1 = tD; }
            float zi = z0 + bgA[0], zf = z1 + bgA[1], zg = z2 + bgA[2], zo = z3 + bgA[3];
            if (FIRST) {
                float xr = Xsh[pa][b];
                zi = fmaf(xr, wxgA[0], zi); zf = fmaf(xr, wxgA[1], zf);
                zg = fmaf(xr, wxgA[2], zg); zo = fmaf(xr, wxgA[3], zo);
            }
            csA = fmaf(sigf(zf), csA, sigf(zi) * fmaxf(zg, 0.0f));
            float h = sigf(zo) * fmaxf(csA, 0.0f);
            __nv_bfloat16 hh = __float2bfloat16(h);
            __nv_bfloat16 hl = __float2bfloat16(h - __bfloat162float(hh));
            __nv_bfloat16* anA = actA + (pa ^ 1) * NB * PA + b * PA;  // a's next h
            anA[KXA + u] = hh; anA[KTA + KXA + u] = hl;
            __nv_bfloat16* xb = actB + pa * NB * PB + b * PB;         // b's x for step tau
            xb[u] = hh; xb[KTB + u] = hl;
            if (FIRST) {
                if (tid < NB) Xsh[pa ^ 1][tid] = xs;
            } else {
                __nv_bfloat16 xh = __float2bfloat16(vx);
                anA[u] = xh;
                anA[KTA + u] = __float2bfloat16(vx - __bfloat162float(xh));
            }
        }
        if (runB) {   // epilogue b (step tau-1)
            float z0 = accB[0] + accB[4], z1 = accB[1] + accB[5];
            float z2 = accB[2] + accB[6], z3 = accB[3] + accB[7];
            const bool t0 = (lane & 4), t1 = (lane & 8);
            float sA = t0 ? z0 : z1, sB = t0 ? z2 : z3;
            float tA = __shfl_xor_sync(~0u, sA, 4), tB = __shfl_xor_sync(~0u, sB, 4);
            if (!t0) { z1 = tA; z3 = tB; } else { z0 = tA; z2 = tB; }
            float sC = t1 ? z0 : z2, sD = t1 ? z1 : z3;
            float tC = __shfl_xor_sync(~0u, sC, 8), tD = __shfl_xor_sync(~0u, sD, 8);
            if (!t1) { z2 = tC; z3 = tD; } else { z0 = tC; z1 = tD; }
            float zi = z0 + bgB[0], zf = z1 + bgB[1], zg = z2 + bgB[2], zo = z3 + bgB[3];
            csB = fmaf(sigf(zf), csB, sigf(zi) * fmaxf(zg, 0.0f));
            float h = sigf(zo) * fmaxf(csB, 0.0f);
            __nv_bfloat16 hh = __float2bfloat16(h);
            __nv_bfloat16* anB = actB + pa * NB * PB + b * PB;        // b's next h
            anB[64 + u] = hh;
            anB[KTB + 64 + u] = __float2bfloat16(h - __bfloat162float(hh));
            if (FIRST)
                g_h1[((size_t)(bg0 + b) * T_LEN + (tau - 1)) * NU + u] = h;
            else if (tau - 1 == T_LEN - 1)
                g_h3[(bg0 + b) * NU + u] = h;
        }
    }
}

__global__ void __launch_bounds__(256)
head_kernel(const float* __restrict__ Wd, const float* __restrict__ bd,
            float* __restrict__ out)
{
    __shared__ float wd[NU];
    if (threadIdx.x < NU) wd[threadIdx.x] = Wd[threadIdx.x];
    __syncthreads();
    int b = blockIdx.x * blockDim.x + threadIdx.x;
    const float* hp = g_h3 + (size_t)b * NU;
    float s = 0.0f;
    #pragma unroll
    for (int u = 0; u < NU; ++u) s += hp[u] * wd[u];
    out[b] = s + bd[0];
}

extern "C" void kernel_launch(void* const* d_in, const int* in_sizes, int n_in,
                              void* d_out, int out_size)
{
    const float* x   = (const float*)d_in[0];
    const float* Wx0 = (const float*)d_in[1];
    const float* U0  = (const float*)d_in[2];
    const float* b0  = (const float*)d_in[3];
    const float* Wx1 = (const float*)d_in[4];
    const float* U1  = (const float*)d_in[5];
    const float* b1  = (const float*)d_in[6];
    const float* Wx2 = (const float*)d_in[7];
    const float* U2  = (const float*)d_in[8];
    const float* b2  = (const float*)d_in[9];
    const float* Wx3 = (const float*)d_in[10];
    const float* U3  = (const float*)d_in[11];
    const float* b3  = (const float*)d_in[12];
    const float* Wd  = (const float*)d_in[13];
    const float* bd  = (const float*)d_in[14];
    float* out = (float*)d_out;

    const int WLO = 2 * 16 * 8 * 32 * 16;
    const int smA = WLO + (2 * NB * (2 * 64 + 8) + 2 * NB * (2 * 128 + 8)) * 2;
    const int smB = WLO + (2 * NB * (2 * 128 + 8) + 2 * NB * (2 * 128 + 8)) * 2;
    cudaFuncSetAttribute((const void*)lstm_pair<0, true>,
                         cudaFuncAttributeMaxDynamicSharedMemorySize, smA);
    cudaFuncSetAttribute((const void*)lstm_pair<64, false>,
                         cudaFuncAttributeMaxDynamicSharedMemorySize, smB);

    lstm_pair<0,  true ><<<128, THR, smA>>>(x,       Wx0, U0, b0, Wx1, U1, b1);
    lstm_pair<64, false><<<128, THR, smB>>>(nullptr, Wx2, U2, b2, Wx3, U3, b3);
    head_kernel<<<B_TOT / 256, 256>>>(Wd, bd, out);
}

// round 14
// speedup vs baseline: 2.3722x; 1.3707x over previous
#include <cuda_runtime.h>
#include <cuda_fp16.h>
#include <cstdint>

#define B_TOT 1024
#define T_LEN 512
#define NU 64
#define NB 8
#define NCTA 128
#define THR 512

__device__ float g_h[(size_t)B_TOT * T_LEN * NU];

__device__ __forceinline__ float sigf(float x) {
    float t; asm("tanh.approx.f32 %0, %1;" : "=f"(t) : "f"(0.5f * x));
    return fmaf(0.5f, t, 0.5f);
}
__device__ __forceinline__ uint32_t pack_h2(__half a, __half b) {
    __half2 p; p.x = a; p.y = b; return *(uint32_t*)&p;
}
__device__ __forceinline__ void hmma(float* c, const uint32_t* a, uint32_t b0, uint32_t b1) {
    asm volatile("mma.sync.aligned.m16n8k16.row.col.f32.f16.f16.f32 "
        "{%0,%1,%2,%3}, {%4,%5,%6,%7}, {%8,%9}, {%0,%1,%2,%3};"
        : "+f"(c[0]), "+f"(c[1]), "+f"(c[2]), "+f"(c[3])
        : "r"(a[0]), "r"(a[1]), "r"(a[2]), "r"(a[3]), "r"(b0), "r"(b1));
}

// R8 skeleton, fp16 2-term: z = Whi*Ahi + Whi*Alo (W fp16 in regs, act hi/lo
// fp16 in smem). Gate-interleaved cols, 8 acc chains (1/k-step, depth 2),
// 4x4 lane transpose, in-register epilogue, double-buffered act, 1 bar/step.
template <int KX, bool LAST>
__global__ void __launch_bounds__(THR, 1)
lstm_layer(const float* __restrict__ xin, const float* __restrict__ Wx,
           const float* __restrict__ U,   const float* __restrict__ bias)
{
    constexpr int KTOT = KX + NU;       // 128 or 64
    constexpr int KS   = KTOT / 16;     // 8 or 4
    constexpr int P    = 2 * KTOT + 8;  // fp16 pitch: hi block | lo block

    __shared__ __half act[2][NB * P];
    __shared__ float Xsh[2][NB];

    const int tid  = threadIdx.x;
    const int wid  = tid >> 5;
    const int lane = tid & 31;
    const int lr   = lane >> 2;
    const int qq   = lane & 3;
    const int aa   = lr >> 2;
    const int gg   = lr & 3;
    const int bg0  = blockIdx.x * NB;

    const int u = 4 * wid + (aa + 2 * (gg >> 1));  // owned unit after transpose
    const int b = 2 * qq + (gg & 1);               // owned batch row

    // ---- W fragments (gate-interleaved columns), fp16 ----
    uint32_t Whi[KS][4];
    {
        const int m0 = 16 * wid + lr;
        #pragma unroll
        for (int s = 0; s < KS; ++s) {
            const int kb = 16 * s + 2 * qq;
            #pragma unroll
            for (int i = 0; i < 4; ++i) {
                const int k = kb + ((i >> 1) << 3);
                const int m = m0 + ((i & 1) << 3);
                const int oc = (m >> 2) + 64 * (m & 3);
                float f0 = (k < KX) ? Wx[(size_t)k * 256 + oc]
                                    : U[(size_t)(k - KX) * 256 + oc];
                float f1 = (k + 1 < KX) ? Wx[(size_t)(k + 1) * 256 + oc]
                                        : U[(size_t)(k + 1 - KX) * 256 + oc];
                Whi[s][i] = pack_h2(__float2half(f0), __float2half(f1));
            }
        }
    }
    float bg[4], wxg[4];
    #pragma unroll
    for (int g = 0; g < 4; ++g) {
        bg[g]  = bias[u + 64 * g];
        wxg[g] = (KX == 0) ? Wx[u + 64 * g] : 0.0f;   // exact fp32 rank-1 x-term
    }

    for (int i = tid; i < 2 * NB * P; i += THR) act[0][i] = __float2half(0.0f);

    // ---- stage step-0 input into buf 0 ----
    float cs = 0.0f;
    if (KX == 0) {
        if (tid < NB) Xsh[0][tid] = xin[(size_t)(bg0 + tid) * T_LEN + 0];
    } else {
        float v0 = g_h[((size_t)(bg0 + b) * T_LEN + 0) * NU + u];
        __half xh = __float2half(v0);
        act[0][b * P + u]        = xh;
        act[0][b * P + KTOT + u] = __float2half(v0 - __half2float(xh));
    }

    for (int t = 0; t < T_LEN; ++t) {
        const int p = t & 1;
        __syncthreads();   // buf[p] complete

        // prefetch step t+1 input (hidden under MMA)
        const int tn = (t + 1 < T_LEN) ? t + 1 : T_LEN - 1;
        float vn = 0.0f, xvn = 0.0f;
        if (KX == 0) {
            if (tid < NB) xvn = xin[(size_t)(bg0 + tid) * T_LEN + tn];
        } else {
            vn = g_h[((size_t)(bg0 + b) * T_LEN + tn) * NU + u];
        }

        // ---- MMA: 2 terms x KS k-steps, one acc chain per k-step ----
        float a8[KS][4];
        #pragma unroll
        for (int s = 0; s < KS; ++s) {
            a8[s][0] = a8[s][1] = a8[s][2] = a8[s][3] = 0.0f;
        }
        const __half* actp = act[p];
        #pragma unroll
        for (int s = 0; s < KS; ++s) {
            const uint32_t* bp = (const uint32_t*)(actp + lr * P + 16 * s + 2 * qq);
            hmma(a8[s], Whi[s], bp[0], bp[4]);                       // hi
            hmma(a8[s], Whi[s], bp[KTOT / 2], bp[KTOT / 2 + 4]);     // lo
        }
        float z0 = 0.0f, z1 = 0.0f, z2 = 0.0f, z3 = 0.0f;
        #pragma unroll
        for (int s = 0; s < KS; ++s) {
            z0 += a8[s][0]; z1 += a8[s][1]; z2 += a8[s][2]; z3 += a8[s][3];
        }

        { // 4x4 lane transpose over lane bits 2-3
            const bool g0 = (lane & 4), g1 = (lane & 8);
            float sA = g0 ? z0 : z1, sB = g0 ? z2 : z3;
            float tA = __shfl_xor_sync(~0u, sA, 4), tB = __shfl_xor_sync(~0u, sB, 4);
            if (!g0) { z1 = tA; z3 = tB; } else { z0 = tA; z2 = tB; }
            float sC = g1 ? z0 : z2, sD = g1 ? z1 : z3;
            float tC = __shfl_xor_sync(~0u, sC, 8), tD = __shfl_xor_sync(~0u, sD, 8);
            if (!g1) { z2 = tC; z3 = tD; } else { z0 = tC; z1 = tD; }
        }

        // ---- epilogue (in registers) ----
        float zi = z0 + bg[0], zf = z1 + bg[1], zg = z2 + bg[2], zo = z3 + bg[3];
        if (KX == 0) {
            float xr = Xsh[p][b];
            zi = fmaf(xr, wxg[0], zi); zf = fmaf(xr, wxg[1], zf);
            zg = fmaf(xr, wxg[2], zg); zo = fmaf(xr, wxg[3], zo);
        }
        float cn = fmaf(sigf(zf), cs, sigf(zi) * fmaxf(zg, 0.0f));
        cs = cn;
        float h = sigf(zo) * fmaxf(cn, 0.0f);

        // ---- write step t+1 operand tile (buf p^1) ----
        __half* an = act[p ^ 1];
        __half hh = __float2half(h);
        an[b * P + KX + u]        = hh;
        an[b * P + KTOT + KX + u] = __float2half(h - __half2float(hh));
        if (KX == 0) {
            if (tid < NB) Xsh[p ^ 1][tid] = xvn;
        } else {
            __half xh = __float2half(vn);
            an[b * P + u]        = xh;
            an[b * P + KTOT + u] = __float2half(vn - __half2float(xh));
        }
        if (!LAST || t == T_LEN - 1)
            g_h[((size_t)(bg0 + b) * T_LEN + t) * NU + u] = h;
    }
}

__global__ void __launch_bounds__(256)
head_kernel(const float* __restrict__ Wd, const float* __restrict__ bd,
            float* __restrict__ out)
{
    __shared__ float wd[NU];
    if (threadIdx.x < NU) wd[threadIdx.x] = Wd[threadIdx.x];
    __syncthreads();
    int b = blockIdx.x * blockDim.x + threadIdx.x;
    const float* hp = g_h + ((size_t)b * T_LEN + (T_LEN - 1)) * NU;
    float s = 0.0f;
    #pragma unroll
    for (int u = 0; u < NU; ++u) s += hp[u] * wd[u];
    out[b] = s + bd[0];
}

extern "C" void kernel_launch(void* const* d_in, const int* in_sizes, int n_in,
                              void* d_out, int out_size)
{
    const float* x   = (const float*)d_in[0];
    const float* Wx0 = (const float*)d_in[1];
    const float* U0  = (const float*)d_in[2];
    const float* b0  = (const float*)d_in[3];
    const float* Wx1 = (const float*)d_in[4];
    const float* U1  = (const float*)d_in[5];
    const float* b1  = (const float*)d_in[6];
    const float* Wx2 = (const float*)d_in[7];
    const float* U2  = (const float*)d_in[8];
    const float* b2  = (const float*)d_in[9];
    const float* Wx3 = (const float*)d_in[10];
    const float* U3  = (const float*)d_in[11];
    const float* b3  = (const float*)d_in[12];
    const float* Wd  = (const float*)d_in[13];
    const float* bd  = (const float*)d_in[14];
    float* out = (float*)d_out;

    lstm_layer<0,  false><<<NCTA, THR>>>(x,       Wx0, U0, b0);
    lstm_layer<64, false><<<NCTA, THR>>>(nullptr, Wx1, U1, b1);
    lstm_layer<64, false><<<NCTA, THR>>>(nullptr, Wx2, U2, b2);
    lstm_layer<64, true ><<<NCTA, THR>>>(nullptr, Wx3, U3, b3);
    head_kernel<<<B_TOT / 256, 256>>>(Wd, bd, out);
}